// round 4
// baseline (speedup 1.0000x reference)
#include <cuda_runtime.h>
#include <cuda_bf16.h>
#include <math.h>
#include <stdint.h>

#define NTOK 16384
#define CDIM 8192
#define HDIM 2048
#define IDIM 8192

// ---------------------------------------------------------------------------
// Scratch (__device__ globals; allocation-free rule)
// ---------------------------------------------------------------------------
__device__ __nv_bfloat16 g_Ah[(size_t)CDIM * HDIM];   // gathered x, hi
__device__ __nv_bfloat16 g_Al[(size_t)CDIM * HDIM];   // gathered x, lo
__device__ __nv_bfloat16 g_Wgh[(size_t)IDIM * HDIM];
__device__ __nv_bfloat16 g_Wgl[(size_t)IDIM * HDIM];
__device__ __nv_bfloat16 g_Wuh[(size_t)IDIM * HDIM];
__device__ __nv_bfloat16 g_Wul[(size_t)IDIM * HDIM];
__device__ __nv_bfloat16 g_Wdh[(size_t)HDIM * IDIM];
__device__ __nv_bfloat16 g_Wdl[(size_t)HDIM * IDIM];
__device__ __nv_bfloat16 g_hh[(size_t)CDIM * IDIM];   // silu(g)*u, hi
__device__ __nv_bfloat16 g_hl[(size_t)CDIM * IDIM];   // silu(g)*u, lo
__device__ float g_down[(size_t)CDIM * HDIM];

// ---------------------------------------------------------------------------
// helpers (plain sm_80-era PTX only — no 'a'-gated features)
// ---------------------------------------------------------------------------
__device__ __forceinline__ uint32_t smem_u32(const void* p) {
    return (uint32_t)__cvta_generic_to_shared(p);
}
__device__ __forceinline__ void ldsm4(uint32_t a, uint32_t* r) {
    asm volatile("ldmatrix.sync.aligned.m8n8.x4.shared.b16 {%0,%1,%2,%3}, [%4];"
                 : "=r"(r[0]), "=r"(r[1]), "=r"(r[2]), "=r"(r[3]) : "r"(a));
}
__device__ __forceinline__ void hmma(float* c, const uint32_t* a,
                                     uint32_t b0, uint32_t b1) {
    asm volatile(
        "mma.sync.aligned.m16n8k16.row.col.f32.bf16.bf16.f32 "
        "{%0,%1,%2,%3},{%4,%5,%6,%7},{%8,%9},{%0,%1,%2,%3};"
        : "+f"(c[0]), "+f"(c[1]), "+f"(c[2]), "+f"(c[3])
        : "r"(a[0]), "r"(a[1]), "r"(a[2]), "r"(a[3]), "r"(b0), "r"(b1));
}
#define CP16(dst, src) \
    asm volatile("cp.async.cg.shared.global [%0], [%1], 16;" \
                 :: "r"(dst), "l"(src))
#define CP_COMMIT() asm volatile("cp.async.commit_group;")
#define CP_WAIT(N)  asm volatile("cp.async.wait_group %0;" :: "n"(N))

__device__ __forceinline__ float silu(float g) { return g / (1.f + expf(-g)); }

// fp32x4 -> 4 bf16 hi (8B) + 4 bf16 lo (8B)
__device__ __forceinline__ void split4(float4 v, uint2& hi, uint2& lo) {
    __nv_bfloat162 h0 = __floats2bfloat162_rn(v.x, v.y);
    __nv_bfloat162 h1 = __floats2bfloat162_rn(v.z, v.w);
    float2 f0 = __bfloat1622float2(h0);
    float2 f1 = __bfloat1622float2(h1);
    __nv_bfloat162 l0 = __floats2bfloat162_rn(v.x - f0.x, v.y - f0.y);
    __nv_bfloat162 l1 = __floats2bfloat162_rn(v.z - f1.x, v.w - f1.y);
    hi = make_uint2(*reinterpret_cast<uint32_t*>(&h0), *reinterpret_cast<uint32_t*>(&h1));
    lo = make_uint2(*reinterpret_cast<uint32_t*>(&l0), *reinterpret_cast<uint32_t*>(&l1));
}

// smem tile: 128 rows x 64 bf16 (128B rows), 16B chunks XOR-swizzled by row.
// fragment address for ldmatrix: plane base + row*128 + ((chunk ^ (row&7))<<4)
#define FR(SB, PL, ROW, S) \
    ((SB) + (PL) + (uint32_t)(ROW) * 128u + \
     ((uint32_t)(((2 * (S) + kHalf) ^ ((ROW) & 7))) << 4))

// k1 smem planes
#define P1_AH 0
#define P1_AL 16384
#define P1_GH 32768
#define P1_GL 49152
#define P1_UH 65536
#define P1_UL 81920
#define STAGE1 98304
#define SMEM1 (2 * STAGE1)     // 192 KB
// k2 smem planes
#define P2_AH 0
#define P2_AL 16384
#define P2_BH 32768
#define P2_BL 49152
#define STAGE2 65536
#define SMEM2 (3 * STAGE2)     // 192 KB

#define NC1 (HDIM / 64)        // 32
#define NC2 (IDIM / 64)        // 128

// ---------------------------------------------------------------------------
// conversion pre-passes
// ---------------------------------------------------------------------------
__global__ __launch_bounds__(256)
void conv_gather(const float* __restrict__ x, const int* __restrict__ fg)
{
    const int c = blockIdx.x;
    const float4* src = reinterpret_cast<const float4*>(
        x + (size_t)__ldg(fg + c) * HDIM);
    const size_t o = (size_t)c * HDIM;
#pragma unroll
    for (int i = threadIdx.x; i < HDIM / 4; i += 256) {
        uint2 hi, lo;
        split4(src[i], hi, lo);
        *reinterpret_cast<uint2*>(g_Ah + o + 4 * i) = hi;
        *reinterpret_cast<uint2*>(g_Al + o + 4 * i) = lo;
    }
}

__global__ __launch_bounds__(256)
void conv_w(const float4* __restrict__ W, __nv_bfloat16* __restrict__ hi,
            __nv_bfloat16* __restrict__ lo, int n4)
{
    for (int i = blockIdx.x * 256 + threadIdx.x; i < n4; i += gridDim.x * 256) {
        uint2 h, l;
        split4(W[i], h, l);
        *reinterpret_cast<uint2*>(hi + 4 * (size_t)i) = h;
        *reinterpret_cast<uint2*>(lo + 4 * (size_t)i) = l;
    }
}

// ---------------------------------------------------------------------------
// Kernel 1: dual GEMM (gate,up), bf16 split-3 HMMA, cp.async pipeline.
// CTA 128 tokens x 128 cols (of both gate & up). Warp = 32m x 64n, both mats.
// ---------------------------------------------------------------------------
__global__ __launch_bounds__(256)
void k1_gateup()
{
    extern __shared__ __align__(128) char sm[];
    const uint32_t smb = smem_u32(sm);
    const int tid  = threadIdx.x;
    const int wid  = tid >> 5;
    const int lane = tid & 31;
    const int m0 = blockIdx.x * 128;   // m fastest: A (64MB planes) ~L2-resident
    const int n0 = blockIdx.y * 128;

    // cp.async geometry: 2 threads/row, 4 chunks each
    const int row   = tid >> 1;
    const int cbase = (tid & 1) * 4;
    const size_t aRow = (size_t)(m0 + row) * HDIM;
    const size_t bRow = (size_t)(n0 + row) * HDIM;
    uint32_t d[4];
#pragma unroll
    for (int j = 0; j < 4; j++)
        d[j] = (uint32_t)(row * 128 + (((cbase + j) ^ (row & 7)) << 4));

#define K1_ISSUE(SB, K0) do {                                                  \
    _Pragma("unroll")                                                          \
    for (int _j = 0; _j < 4; _j++) {                                           \
        const int ke = (K0) + (cbase + _j) * 8;                                \
        CP16((SB) + P1_AH + d[_j], g_Ah  + aRow + ke);                         \
        CP16((SB) + P1_AL + d[_j], g_Al  + aRow + ke);                         \
        CP16((SB) + P1_GH + d[_j], g_Wgh + bRow + ke);                         \
        CP16((SB) + P1_GL + d[_j], g_Wgl + bRow + ke);                         \
        CP16((SB) + P1_UH + d[_j], g_Wuh + bRow + ke);                         \
        CP16((SB) + P1_UL + d[_j], g_Wul + bRow + ke);                         \
    }                                                                          \
    CP_COMMIT();                                                               \
} while (0)

    // ldmatrix lane geometry
    const int laneRow = ((lane >> 3) & 1) * 8 + (lane & 7);
    const int kHalf   = lane >> 4;
    const int Rw = 32 * (wid & 3);
    const int Cb = 64 * (wid >> 2);

    float accg[2][8][4], accu[2][8][4];
#pragma unroll
    for (int f = 0; f < 2; f++)
#pragma unroll
        for (int n = 0; n < 8; n++)
#pragma unroll
            for (int q = 0; q < 4; q++) { accg[f][n][q] = 0.f; accu[f][n][q] = 0.f; }

    K1_ISSUE(smb, 0);

#pragma unroll 1
    for (int c = 0; c < NC1; c++) {
        const uint32_t sb = smb + (uint32_t)(c & 1) * STAGE1;
        CP_WAIT(0);
        __syncthreads();
        if (c + 1 < NC1)
            K1_ISSUE(smb + (uint32_t)((c + 1) & 1) * STAGE1, (c + 1) * 64);

#pragma unroll
        for (int s = 0; s < 4; s++) {
            uint32_t ah[2][4], al[2][4];
            const int r0 = Rw + laneRow;
            ldsm4(FR(sb, P1_AH, r0,      s), ah[0]);
            ldsm4(FR(sb, P1_AH, r0 + 16, s), ah[1]);
            ldsm4(FR(sb, P1_AL, r0,      s), al[0]);
            ldsm4(FR(sb, P1_AL, r0 + 16, s), al[1]);
#pragma unroll
            for (int gp = 0; gp < 4; gp++) {
                const int br = Cb + 16 * gp + laneRow;
                uint32_t gh[4], gl[4], uh[4], ul[4];
                ldsm4(FR(sb, P1_GH, br, s), gh);
                ldsm4(FR(sb, P1_GL, br, s), gl);
                ldsm4(FR(sb, P1_UH, br, s), uh);
                ldsm4(FR(sb, P1_UL, br, s), ul);
#pragma unroll
                for (int f = 0; f < 2; f++)
#pragma unroll
                    for (int h = 0; h < 2; h++) {
                        float* cg = accg[f][2 * gp + h];
                        hmma(cg, ah[f], gh[h], gh[2 + h]);
                        hmma(cg, ah[f], gl[h], gl[2 + h]);
                        hmma(cg, al[f], gh[h], gh[2 + h]);
                        float* cu = accu[f][2 * gp + h];
                        hmma(cu, ah[f], uh[h], uh[2 + h]);
                        hmma(cu, ah[f], ul[h], ul[2 + h]);
                        hmma(cu, al[f], uh[h], uh[2 + h]);
                    }
            }
        }
        __syncthreads();
    }

    // warp-local epilogue: silu(g)*u -> hi/lo bf16 planes of g_h
#pragma unroll
    for (int f = 0; f < 2; f++)
#pragma unroll
        for (int n = 0; n < 8; n++) {
            const int r  = m0 + Rw + 16 * f + (lane >> 2);
            const int cc = n0 + Cb + 8 * n + (lane & 3) * 2;
            {
                float v0 = silu(accg[f][n][0]) * accu[f][n][0];
                float v1 = silu(accg[f][n][1]) * accu[f][n][1];
                __nv_bfloat162 h = __floats2bfloat162_rn(v0, v1);
                float2 hf = __bfloat1622float2(h);
                __nv_bfloat162 l = __floats2bfloat162_rn(v0 - hf.x, v1 - hf.y);
                *reinterpret_cast<uint32_t*>(g_hh + (size_t)r * IDIM + cc) =
                    *reinterpret_cast<uint32_t*>(&h);
                *reinterpret_cast<uint32_t*>(g_hl + (size_t)r * IDIM + cc) =
                    *reinterpret_cast<uint32_t*>(&l);
            }
            {
                float v0 = silu(accg[f][n][2]) * accu[f][n][2];
                float v1 = silu(accg[f][n][3]) * accu[f][n][3];
                __nv_bfloat162 h = __floats2bfloat162_rn(v0, v1);
                float2 hf = __bfloat1622float2(h);
                __nv_bfloat162 l = __floats2bfloat162_rn(v0 - hf.x, v1 - hf.y);
                *reinterpret_cast<uint32_t*>(g_hh + (size_t)(r + 8) * IDIM + cc) =
                    *reinterpret_cast<uint32_t*>(&h);
                *reinterpret_cast<uint32_t*>(g_hl + (size_t)(r + 8) * IDIM + cc) =
                    *reinterpret_cast<uint32_t*>(&l);
            }
        }
}

// ---------------------------------------------------------------------------
// Kernel 2: down projection, bf16 split-3 HMMA, 3-stage cp.async pipeline.
// CTA 128 x 128; warp 32m x 64n.
// ---------------------------------------------------------------------------
__global__ __launch_bounds__(256)
void k2_down()
{
    extern __shared__ __align__(128) char sm[];
    const uint32_t smb = smem_u32(sm);
    const int tid  = threadIdx.x;
    const int wid  = tid >> 5;
    const int lane = tid & 31;
    const int n0 = blockIdx.x * 128;   // n fastest: Wd planes stay L2-resident
    const int m0 = blockIdx.y * 128;

    const int row   = tid >> 1;
    const int cbase = (tid & 1) * 4;
    const size_t aRow = (size_t)(m0 + row) * IDIM;
    const size_t bRow = (size_t)(n0 + row) * IDIM;
    uint32_t d[4];
#pragma unroll
    for (int j = 0; j < 4; j++)
        d[j] = (uint32_t)(row * 128 + (((cbase + j) ^ (row & 7)) << 4));

#define K2_ISSUE(SB, K0) do {                                                  \
    _Pragma("unroll")                                                          \
    for (int _j = 0; _j < 4; _j++) {                                           \
        const int ke = (K0) + (cbase + _j) * 8;                                \
        CP16((SB) + P2_AH + d[_j], g_hh  + aRow + ke);                         \
        CP16((SB) + P2_AL + d[_j], g_hl  + aRow + ke);                         \
        CP16((SB) + P2_BH + d[_j], g_Wdh + bRow + ke);                         \
        CP16((SB) + P2_BL + d[_j], g_Wdl + bRow + ke);                         \
    }                                                                          \
    CP_COMMIT();                                                               \
} while (0)

    const int laneRow = ((lane >> 3) & 1) * 8 + (lane & 7);
    const int kHalf   = lane >> 4;
    const int Rw = 32 * (wid & 3);
    const int Cb = 64 * (wid >> 2);

    float acc[2][8][4];
#pragma unroll
    for (int f = 0; f < 2; f++)
#pragma unroll
        for (int n = 0; n < 8; n++)
#pragma unroll
            for (int q = 0; q < 4; q++) acc[f][n][q] = 0.f;

    K2_ISSUE(smb, 0);
    K2_ISSUE(smb + STAGE2, 64);

#pragma unroll 1
    for (int c = 0; c < NC2; c++) {
        const uint32_t sb = smb + (uint32_t)(c % 3) * STAGE2;
        if (c + 2 < NC2) { CP_WAIT(1); } else { CP_WAIT(0); }
        __syncthreads();
        if (c + 2 < NC2)
            K2_ISSUE(smb + (uint32_t)((c + 2) % 3) * STAGE2, (c + 2) * 64);

#pragma unroll
        for (int s = 0; s < 4; s++) {
            uint32_t ah[2][4], al[2][4];
            const int r0 = Rw + laneRow;
            ldsm4(FR(sb, P2_AH, r0,      s), ah[0]);
            ldsm4(FR(sb, P2_AH, r0 + 16, s), ah[1]);
            ldsm4(FR(sb, P2_AL, r0,      s), al[0]);
            ldsm4(FR(sb, P2_AL, r0 + 16, s), al[1]);
#pragma unroll
            for (int gp = 0; gp < 4; gp++) {
                const int br = Cb + 16 * gp + laneRow;
                uint32_t bh[4], bl[4];
                ldsm4(FR(sb, P2_BH, br, s), bh);
                ldsm4(FR(sb, P2_BL, br, s), bl);
#pragma unroll
                for (int f = 0; f < 2; f++)
#pragma unroll
                    for (int h = 0; h < 2; h++) {
                        float* cc = acc[f][2 * gp + h];
                        hmma(cc, ah[f], bh[h], bh[2 + h]);
                        hmma(cc, ah[f], bl[h], bl[2 + h]);
                        hmma(cc, al[f], bh[h], bh[2 + h]);
                    }
            }
        }
        __syncthreads();
    }

    // epilogue: fp32 stores
#pragma unroll
    for (int f = 0; f < 2; f++)
#pragma unroll
        for (int n = 0; n < 8; n++) {
            const int r  = m0 + Rw + 16 * f + (lane >> 2);
            const int cc = n0 + Cb + 8 * n + (lane & 3) * 2;
            *reinterpret_cast<float2*>(g_down + (size_t)r * HDIM + cc) =
                make_float2(acc[f][n][0], acc[f][n][1]);
            *reinterpret_cast<float2*>(g_down + (size_t)(r + 8) * HDIM + cc) =
                make_float2(acc[f][n][2], acc[f][n][3]);
        }
}

// ---------------------------------------------------------------------------
// Kernel 3: scatter compact rows to all original token slots
// ---------------------------------------------------------------------------
__global__ __launch_bounds__(256)
void scatter_kernel(const int* __restrict__ scatter_indices,
                    float* __restrict__ out)
{
    const int t = blockIdx.x;
    const int c = scatter_indices[t];
    const float4* src = reinterpret_cast<const float4*>(g_down + (size_t)c * HDIM);
    float4*       dst = reinterpret_cast<float4*>(out + (size_t)t * HDIM);
#pragma unroll
    for (int j = threadIdx.x; j < HDIM / 4; j += 256)
        dst[j] = src[j];
}

// ---------------------------------------------------------------------------
extern "C" void kernel_launch(void* const* d_in, const int* in_sizes, int n_in,
                              void* d_out, int out_size)
{
    const float* x  = (const float*)d_in[0];
    const float* Wg = (const float*)d_in[1];
    const float* Wu = (const float*)d_in[2];
    const float* Wd = (const float*)d_in[3];
    const int*   fg = (const int*)d_in[4];
    const int*   sc = (const int*)d_in[5];
    float*       out = (float*)d_out;

    cudaFuncSetAttribute(k1_gateup, cudaFuncAttributeMaxDynamicSharedMemorySize, SMEM1);
    cudaFuncSetAttribute(k2_down,   cudaFuncAttributeMaxDynamicSharedMemorySize, SMEM2);

    __nv_bfloat16 *wgh, *wgl, *wuh, *wul, *wdh, *wdl;
    cudaGetSymbolAddress((void**)&wgh, g_Wgh);
    cudaGetSymbolAddress((void**)&wgl, g_Wgl);
    cudaGetSymbolAddress((void**)&wuh, g_Wuh);
    cudaGetSymbolAddress((void**)&wul, g_Wul);
    cudaGetSymbolAddress((void**)&wdh, g_Wdh);
    cudaGetSymbolAddress((void**)&wdl, g_Wdl);

    // pre-passes
    conv_gather<<<CDIM, 256>>>(x, fg);
    const int n4 = (IDIM * HDIM) / 4;  // 4M float4 per weight
    conv_w<<<4096, 256>>>((const float4*)Wg, wgh, wgl, n4);
    conv_w<<<4096, 256>>>((const float4*)Wu, wuh, wul, n4);
    conv_w<<<4096, 256>>>((const float4*)Wd, wdh, wdl, n4);

    dim3 g1(CDIM / 128, IDIM / 128);   // (64 m fastest, 64 n)
    k1_gateup<<<g1, 256, SMEM1>>>();

    dim3 g2(HDIM / 128, CDIM / 128);   // (16 n fastest, 64 m)
    k2_down<<<g2, 256, SMEM2>>>();

    scatter_kernel<<<NTOK, 256>>>(sc, out);
}